// round 14
// baseline (speedup 1.0000x reference)
#include <cuda_runtime.h>
#include <cuda_bf16.h>
#include <cstdint>
#include <cstddef>

// ===================== problem constants =====================
#define N_ROIS   128
#define N_CH     512
#define FH       37
#define FW       37
#define K_FC6    25088      // 512*7*7
#define NFC      4096
#define KSPLIT   4

// ===================== static scratch =====================
__device__ __align__(256) float g_pooled[N_ROIS * K_FC6];
__device__ __align__(256) float g_fc6[N_ROIS * NFC];
__device__ __align__(256) float g_fc7[N_ROIS * NFC];
__device__ __align__(256) float g_part[KSPLIT * N_ROIS * NFC];

// ===================== helpers =====================
__device__ __forceinline__ uint32_t smem_u32(const void* p) {
    uint32_t a;
    asm("{ .reg .u64 t; cvta.to.shared.u64 t, %1; cvt.u32.u64 %0, t; }" : "=r"(a) : "l"(p));
    return a;
}

__device__ __forceinline__ void split2_pair(float a, float b, uint32_t& h, uint32_t& l) {
    __nv_bfloat16 ha = __float2bfloat16_rn(a), hb = __float2bfloat16_rn(b);
    __nv_bfloat16 la = __float2bfloat16_rn(a - __bfloat162float(ha));
    __nv_bfloat16 lb = __float2bfloat16_rn(b - __bfloat162float(hb));
    h = (uint32_t)__bfloat16_as_ushort(ha) | ((uint32_t)__bfloat16_as_ushort(hb) << 16);
    l = (uint32_t)__bfloat16_as_ushort(la) | ((uint32_t)__bfloat16_as_ushort(lb) << 16);
}

__device__ __forceinline__ void mma16816(float* d, const uint32_t* a, const uint32_t* b) {
    asm volatile(
        "mma.sync.aligned.m16n8k16.row.col.f32.bf16.bf16.f32 "
        "{%0,%1,%2,%3}, {%4,%5,%6,%7}, {%8,%9}, {%0,%1,%2,%3};"
        : "+f"(d[0]), "+f"(d[1]), "+f"(d[2]), "+f"(d[3])
        : "r"(a[0]), "r"(a[1]), "r"(a[2]), "r"(a[3]), "r"(b[0]), "r"(b[1]));
}

#define LDSM4(R, ADDR) \
    asm volatile("ldmatrix.sync.aligned.m8n8.x4.shared.b16 {%0,%1,%2,%3}, [%4];" \
        : "=r"((R)[0]), "=r"((R)[1]), "=r"((R)[2]), "=r"((R)[3]) : "r"(ADDR))

// ===================== GEMM: CTA tile M128 x N128, 256 thr (2x4 warps, warp tile 64x32) =====================
// 1 CTA/SM, 255-reg budget. Register-staged prefetch TWO stages ahead:
//   stage s: ldgAB(s+2) -> compute ks0(s) -> stsAB(s+1) -> compute ks1(s) -> bar
// LDG slack ~1.5 stages >> DRAM latency. Double-buffered smem (2 x 40960 B).
__global__ __launch_bounds__(256, 1)
void gemm_bf16x3(const float* __restrict__ A, const float* __restrict__ B,
                 float* __restrict__ P, int K, int Kchunk, int Ntot, int n_tiles)
{
    extern __shared__ uint32_t sm[];
    constexpr uint32_t STG32 = 10240;                 // b32 words per stage
    constexpr uint32_t A_L32 = 2560, B_H32 = 5120, B_L32 = 7680;
    constexpr uint32_t STG_BYTES = 40960;

    const int t = threadIdx.x;
    const int wid = t >> 5, lid = t & 31;
    const int wm = wid & 1, wn = wid >> 1;            // 2 x 4 warp grid; warp tile 64 x 32
    const int ntile = blockIdx.x % n_tiles;
    const int ksp = blockIdx.x / n_tiles;
    const int k_begin = ksp * Kchunk;
    const int S = Kchunk >> 5;

    const float* Bt = B + (size_t)(ntile * 128) * K;
    const int r2 = t >> 1, c2 = t & 1;                // loader: row 0..127, 16-float half

    const int aRow = lid & 15;
    const int aK8 = (lid >> 4) & 1;
    const int bRow = (lid & 7) | ((lid & 16) >> 1);
    const int bK8 = (lid >> 3) & 1;

    const uint32_t sb = smem_u32(sm);

    float acc[4][4][4];
#pragma unroll
    for (int i = 0; i < 4; ++i)
#pragma unroll
        for (int j = 0; j < 4; ++j)
#pragma unroll
            for (int q = 0; q < 4; ++q) acc[i][j][q] = 0.0f;

    float4 stgA[2][4], stgB[2][4];   // two staging sets (A: 16 floats, B: 16 floats each)

    auto ldgAB = [&](int k0, int set) {
        const float* pa = A + (size_t)r2 * K + k0 + c2 * 16;
#pragma unroll
        for (int j = 0; j < 4; ++j) stgA[set][j] = *reinterpret_cast<const float4*>(pa + j * 4);
        const float* pb = Bt + (size_t)r2 * K + k0 + c2 * 16;
#pragma unroll
        for (int j = 0; j < 4; ++j) stgB[set][j] = *reinterpret_cast<const float4*>(pb + j * 4);
    };

    auto sts16 = [&](const float4* stg, uint32_t* hiBase, uint32_t* loBase) {
        float f[16] = {stg[0].x, stg[0].y, stg[0].z, stg[0].w,
                       stg[1].x, stg[1].y, stg[1].z, stg[1].w,
                       stg[2].x, stg[2].y, stg[2].z, stg[2].w,
                       stg[3].x, stg[3].y, stg[3].z, stg[3].w};
        uint32_t hv[8], lv[8];
#pragma unroll
        for (int j = 0; j < 8; ++j) split2_pair(f[2 * j], f[2 * j + 1], hv[j], lv[j]);
        const int o = r2 * 20 + c2 * 8;
        *reinterpret_cast<uint4*>(hiBase + o)     = make_uint4(hv[0], hv[1], hv[2], hv[3]);
        *reinterpret_cast<uint4*>(hiBase + o + 4) = make_uint4(hv[4], hv[5], hv[6], hv[7]);
        *reinterpret_cast<uint4*>(loBase + o)     = make_uint4(lv[0], lv[1], lv[2], lv[3]);
        *reinterpret_cast<uint4*>(loBase + o + 4) = make_uint4(lv[4], lv[5], lv[6], lv[7]);
    };
    auto stsAB = [&](int set, int buf) {
        uint32_t* s = sm + buf * STG32;
        sts16(stgA[set], s, s + A_L32);
        sts16(stgB[set], s + B_H32, s + B_L32);
    };

    auto compute_ks = [&](int buf, int ks) {
        const uint32_t base = sb + (uint32_t)buf * STG_BYTES;
        uint32_t bh[2][4], bl[2][4];
#pragma unroll
        for (int ntp = 0; ntp < 2; ++ntp) {
            uint32_t boff = (uint32_t)(((wn * 32 + ntp * 16 + bRow) * 40 + ks * 16 + bK8 * 8) * 2);
            LDSM4(bh[ntp], base + B_H32 * 4 + boff);
            LDSM4(bl[ntp], base + B_L32 * 4 + boff);
        }
#pragma unroll
        for (int mt = 0; mt < 4; ++mt) {
            uint32_t aoff = (uint32_t)(((wm * 64 + mt * 16 + aRow) * 40 + ks * 16 + aK8 * 8) * 2);
            uint32_t ah[4], al[4];
            LDSM4(ah, base + aoff);
            LDSM4(al, base + A_L32 * 4 + aoff);
#pragma unroll
            for (int ntp = 0; ntp < 2; ++ntp) {
                float* d0 = acc[mt][2 * ntp];
                float* d1 = acc[mt][2 * ntp + 1];
                mma16816(d0, ah, bh[ntp]);     mma16816(d1, ah, bh[ntp] + 2);
                mma16816(d0, ah, bl[ntp]);     mma16816(d1, ah, bl[ntp] + 2);
                mma16816(d0, al, bh[ntp]);     mma16816(d1, al, bh[ntp] + 2);
            }
        }
    };

    // prologue: stage0 -> smem buf0; stage1 staged in regs (set1)
    ldgAB(k_begin, 0);
    stsAB(0, 0);
    if (S > 1) ldgAB(k_begin + 32, 1);
    __syncthreads();

    for (int s = 0; s < S; ++s) {
        if (s + 2 < S) ldgAB(k_begin + (s + 2) * 32, s & 1);     // into set freed last stage
        compute_ks(s & 1, 0);
        if (s + 1 < S) stsAB((s + 1) & 1, (s + 1) & 1);           // stage s+1 regs -> other buf
        compute_ks(s & 1, 1);
        __syncthreads();
    }

    // epilogue: fp32 partials
    const int g = lid >> 2, tig = lid & 3;
    float* Pbase = P + (size_t)(ksp * 128) * Ntot + ntile * 128;
#pragma unroll
    for (int mt = 0; mt < 4; ++mt) {
#pragma unroll
        for (int nt = 0; nt < 4; ++nt) {
            int row = wm * 64 + mt * 16 + g;
            int col = wn * 32 + nt * 8 + tig * 2;
            float* d0 = Pbase + (size_t)row * Ntot + col;
            float* d1 = Pbase + (size_t)(row + 8) * Ntot + col;
            *reinterpret_cast<float2*>(d0) = make_float2(acc[mt][nt][0], acc[mt][nt][1]);
            *reinterpret_cast<float2*>(d1) = make_float2(acc[mt][nt][2], acc[mt][nt][3]);
        }
    }
}

// ===================== RoI max pool — reciprocal-division emulation (LOAD-BEARING) =====================
__global__ void roipool_kernel(const float* __restrict__ x, const float* __restrict__ rois,
                               const int* __restrict__ ridx, float* __restrict__ pooled) {
    const int r = blockIdx.x;
    const float C7 = __uint_as_float(0x3E124925u);  // fl(1/7): matches XLA reciprocal-multiply
    __shared__ int hs[7], he[7], ws_[7], we_[7];
    if (threadIdx.x < 7) {
        const int p = threadIdx.x;
        float y1 = rintf(rois[r * 4 + 0] * 0.0625f);
        float x1 = rintf(rois[r * 4 + 1] * 0.0625f);
        float y2 = rintf(rois[r * 4 + 2] * 0.0625f);
        float x2 = rintf(rois[r * 4 + 3] * 0.0625f);
        float rh = fmaxf(y2 - y1 + 1.0f, 1.0f);
        float rw = fmaxf(x2 - x1 + 1.0f, 1.0f);
        float pf = (float)p;
        hs[p]  = (int)fminf(fmaxf(y1 + floorf((pf * rh) * C7), 0.0f), 37.0f);
        he[p]  = (int)fminf(fmaxf(y1 + ceilf(((pf + 1.0f) * rh) * C7), 0.0f), 37.0f);
        ws_[p] = (int)fminf(fmaxf(x1 + floorf((pf * rw) * C7), 0.0f), 37.0f);
        we_[p] = (int)fminf(fmaxf(x1 + ceilf(((pf + 1.0f) * rw) * C7), 0.0f), 37.0f);
    }
    __syncthreads();
    const float* xb = x + (size_t)ridx[r] * N_CH * (FH * FW);
    const float NEG = __int_as_float(0xff800000);
    for (int q = threadIdx.x; q < N_CH * 49; q += blockDim.x) {
        const int c = q / 49;
        const int b = q - c * 49;
        const int ph = b / 7, pw = b - ph * 7;
        const float* xc = xb + c * (FH * FW);
        float mx = NEG;
        for (int h = hs[ph]; h < he[ph]; ++h) {
            const float* xr = xc + h * FW;
            for (int w = ws_[pw]; w < we_[pw]; ++w) mx = fmaxf(mx, xr[w]);
        }
        pooled[(size_t)r * K_FC6 + q] = (mx == NEG) ? 0.0f : mx;
    }
}

// ===================== reduce: sum split-K partials + bias + relu =====================
__global__ void reduce_kernel(const float* __restrict__ P, const float* __restrict__ bias,
                              float* __restrict__ out) {
    int idx = blockIdx.x * blockDim.x + threadIdx.x;
    if (idx >= 128 * NFC) return;
    int n = idx & (NFC - 1);
    float v = 0.0f;
#pragma unroll
    for (int s = 0; s < KSPLIT; ++s) v += P[(size_t)s * 128 * NFC + idx];
    out[idx] = fmaxf(v + bias[n], 0.0f);
}

// ===================== heads =====================
__global__ __launch_bounds__(256)
void heads_kernel(const float* __restrict__ fc7,
                  const float* __restrict__ Wsc, const float* __restrict__ bsc,
                  const float* __restrict__ Wloc, const float* __restrict__ bloc,
                  float* __restrict__ out) {
    int gw = (blockIdx.x * 256 + threadIdx.x) >> 5;
    int lane = threadIdx.x & 31;
    if (gw >= 128 * 105) return;
    int m = gw / 105, c = gw - m * 105;
    const float* wr = (c < 21) ? (Wsc + (size_t)c * NFC) : (Wloc + (size_t)(c - 21) * NFC);
    const float* arow = fc7 + (size_t)m * NFC;
    float s = 0.0f;
#pragma unroll 4
    for (int k = lane * 4; k < NFC; k += 128) {
        float4 a = *reinterpret_cast<const float4*>(arow + k);
        float4 w = *reinterpret_cast<const float4*>(wr + k);
        s += a.x * w.x + a.y * w.y + a.z * w.z + a.w * w.w;
    }
#pragma unroll
    for (int o = 16; o; o >>= 1) s += __shfl_down_sync(0xffffffffu, s, o);
    if (lane == 0) {
        if (c < 21) out[m * 21 + c] = s + bsc[c];
        else        out[128 * 21 + m * 84 + (c - 21)] = s + bloc[c - 21];
    }
}

// ===================== launch =====================
extern "C" void kernel_launch(void* const* d_in, const int* in_sizes, int n_in,
                              void* d_out, int out_size) {
    const float *x = nullptr, *rois = nullptr, *W1 = nullptr, *b1 = nullptr, *W2 = nullptr,
                *b2 = nullptr, *Wloc = nullptr, *bloc = nullptr, *Wsc = nullptr, *bsc = nullptr;
    const int* ridx = nullptr;
    for (int i = 0; i < n_in; ++i) {
        const int sz = in_sizes[i];
        const float* p = (const float*)d_in[i];
        switch (sz) {
            case 2 * N_CH * FH * FW: x = p; break;
            case N_ROIS * 4:         rois = p; break;
            case N_ROIS:             ridx = (const int*)d_in[i]; break;
            case NFC * K_FC6:        W1 = p; break;
            case NFC * NFC:          W2 = p; break;
            case 84 * NFC:           Wloc = p; break;
            case 21 * NFC:           Wsc = p; break;
            case 84:                 bloc = p; break;
            case 21:                 bsc = p; break;
            case NFC:                if (!b1) b1 = p; else b2 = p; break;
            default: break;
        }
    }
    float* out = (float*)d_out;

    float *pooled, *fc6, *fc7, *part;
    cudaGetSymbolAddress((void**)&pooled, g_pooled);
    cudaGetSymbolAddress((void**)&fc6, g_fc6);
    cudaGetSymbolAddress((void**)&fc7, g_fc7);
    cudaGetSymbolAddress((void**)&part, g_part);

    const int smem_gemm = 2 * 40960;  // 81920 B
    cudaFuncSetAttribute((const void*)gemm_bf16x3,
                         cudaFuncAttributeMaxDynamicSharedMemorySize, smem_gemm);

    // 1. RoI max pool
    roipool_kernel<<<N_ROIS, 256>>>(x, rois, ridx, pooled);
    // 2. fc6: 32 ntiles x 4 ksplit = 128 CTAs (1 CTA/SM)
    gemm_bf16x3<<<32 * KSPLIT, 256, smem_gemm>>>(pooled, W1, part, K_FC6, K_FC6 / KSPLIT, NFC, 32);
    reduce_kernel<<<(128 * NFC + 255) / 256, 256>>>(part, b1, fc6);
    // 3. fc7
    gemm_bf16x3<<<32 * KSPLIT, 256, smem_gemm>>>(fc6, W2, part, NFC, NFC / KSPLIT, NFC, 32);
    reduce_kernel<<<(128 * NFC + 255) / 256, 256>>>(part, b2, fc7);
    // 4. heads
    heads_kernel<<<(128 * 105 * 32 + 255) / 256, 256>>>(fc7, Wsc, bsc, Wloc, bloc, out);
}

// round 17
// speedup vs baseline: 1.9874x; 1.9874x over previous
#include <cuda_runtime.h>
#include <cuda_bf16.h>
#include <cstdint>
#include <cstddef>

// ===================== problem constants =====================
#define N_ROIS   128
#define N_CH     512
#define FH       37
#define FW       37
#define K_FC6    25088      // 512*7*7
#define NFC      4096
#define KSPLIT   8

// ===================== static scratch =====================
__device__ __align__(256) float g_pooled[N_ROIS * K_FC6];
__device__ __align__(256) float g_fc6[N_ROIS * NFC];
__device__ __align__(256) float g_fc7[N_ROIS * NFC];
__device__ __align__(256) float g_part[KSPLIT * N_ROIS * NFC];

// ===================== helpers =====================
__device__ __forceinline__ uint32_t smem_u32(const void* p) {
    uint32_t a;
    asm("{ .reg .u64 t; cvta.to.shared.u64 t, %1; cvt.u32.u64 %0, t; }" : "=r"(a) : "l"(p));
    return a;
}

__device__ __forceinline__ void split2_pair(float a, float b, uint32_t& h, uint32_t& l) {
    __nv_bfloat16 ha = __float2bfloat16_rn(a), hb = __float2bfloat16_rn(b);
    __nv_bfloat16 la = __float2bfloat16_rn(a - __bfloat162float(ha));
    __nv_bfloat16 lb = __float2bfloat16_rn(b - __bfloat162float(hb));
    h = (uint32_t)__bfloat16_as_ushort(ha) | ((uint32_t)__bfloat16_as_ushort(hb) << 16);
    l = (uint32_t)__bfloat16_as_ushort(la) | ((uint32_t)__bfloat16_as_ushort(lb) << 16);
}

__device__ __forceinline__ void mma16816(float* d, const uint32_t* a, const uint32_t* b) {
    asm volatile(
        "mma.sync.aligned.m16n8k16.row.col.f32.bf16.bf16.f32 "
        "{%0,%1,%2,%3}, {%4,%5,%6,%7}, {%8,%9}, {%0,%1,%2,%3};"
        : "+f"(d[0]), "+f"(d[1]), "+f"(d[2]), "+f"(d[3])
        : "r"(a[0]), "r"(a[1]), "r"(a[2]), "r"(a[3]), "r"(b[0]), "r"(b[1]));
}

#define LDSM4(R, ADDR) \
    asm volatile("ldmatrix.sync.aligned.m8n8.x4.shared.b16 {%0,%1,%2,%3}, [%4];" \
        : "=r"((R)[0]), "=r"((R)[1]), "=r"((R)[2]), "=r"((R)[3]) : "r"(ADDR))

__device__ __forceinline__ void cp16(uint32_t saddr, const void* g) {
    asm volatile("cp.async.cg.shared.global [%0], [%1], 16;" :: "r"(saddr), "l"(g) : "memory");
}
#define CP_COMMIT() asm volatile("cp.async.commit_group;" ::: "memory")
#define CP_WAIT0()  asm volatile("cp.async.wait_group 0;" ::: "memory")

// ===================== GEMM: CTA tile M128 x N128, 256 thr (2x4 warps, warp tile 64x32) =====================
// 2 CTAs/SM. A via cp.async (full-stage slack), B register-staged one stage early.
// Stage s: compute ks0 | CP_WAIT0 | BAR (cross-thread cp.async visibility!) |
//          convertA(s+1)+stsB(s+1) | compute ks1 | BAR | cpA(s+2), ldgB(s+2)
// smem/CTA: bf16 planes 2x40960 + fp32 A buffer 16384 = 98304 B.
__global__ __launch_bounds__(256, 2)
void gemm_bf16x3(const float* __restrict__ A, const float* __restrict__ B,
                 float* __restrict__ P, int K, int Kchunk, int Ntot, int n_tiles)
{
    extern __shared__ uint32_t sm[];
    constexpr uint32_t STG32 = 10240;                 // b32 words per bf16-plane stage
    constexpr uint32_t A_L32 = 2560, B_H32 = 5120, B_L32 = 7680;
    constexpr uint32_t STG_BYTES = 40960;
    constexpr uint32_t FA32 = 2 * STG32;              // fp32 A buffer (b32 offset 20480)

    const int t = threadIdx.x;
    const int wid = t >> 5, lid = t & 31;
    const int wm = wid & 1, wn = wid >> 1;            // 2 x 4 warp grid; warp tile 64 x 32
    const int ntile = blockIdx.x % n_tiles;
    const int ksp = blockIdx.x / n_tiles;
    const int k_begin = ksp * Kchunk;
    const int S = Kchunk >> 5;

    const float* Bt = B + (size_t)(ntile * 128) * K;
    const int r2 = t >> 1, c2 = t & 1;                // 128 rows, 16-float half

    const int aRow = lid & 15;
    const int aK8 = (lid >> 4) & 1;
    const int bRow = (lid & 7) | ((lid & 16) >> 1);
    const int bK8 = (lid >> 3) & 1;

    const uint32_t sb = smem_u32(sm);

    float acc[4][4][4];
#pragma unroll
    for (int i = 0; i < 4; ++i)
#pragma unroll
        for (int j = 0; j < 4; ++j)
#pragma unroll
            for (int q = 0; q < 4; ++q) acc[i][j][q] = 0.0f;

    float4 stgB[4];   // single static staging set: 16 floats of B

    auto cpA = [&](int k0) {   // A tile 128 x 32 fp32 -> F_A (row-major, 128 B rows)
#pragma unroll
        for (int j = 0; j < 4; ++j) {
            int id = t + j * 256;
            cp16(sb + FA32 * 4 + (id >> 3) * 128 + (id & 7) * 16,
                 A + (size_t)(id >> 3) * K + k0 + (id & 7) * 4);
        }
    };
    auto ldgB = [&](int k0) {
        const float* pb = Bt + (size_t)r2 * K + k0 + c2 * 16;
#pragma unroll
        for (int j = 0; j < 4; ++j) stgB[j] = *reinterpret_cast<const float4*>(pb + j * 4);
    };

    auto sts16 = [&](const float* f, uint32_t* hiBase, uint32_t* loBase) {
        uint32_t hv[8], lv[8];
#pragma unroll
        for (int j = 0; j < 8; ++j) split2_pair(f[2 * j], f[2 * j + 1], hv[j], lv[j]);
        const int o = r2 * 20 + c2 * 8;
        *reinterpret_cast<uint4*>(hiBase + o)     = make_uint4(hv[0], hv[1], hv[2], hv[3]);
        *reinterpret_cast<uint4*>(hiBase + o + 4) = make_uint4(hv[4], hv[5], hv[6], hv[7]);
        *reinterpret_cast<uint4*>(loBase + o)     = make_uint4(lv[0], lv[1], lv[2], lv[3]);
        *reinterpret_cast<uint4*>(loBase + o + 4) = make_uint4(lv[4], lv[5], lv[6], lv[7]);
    };
    auto convertA = [&](int buf) {   // F_A fp32 -> A hi/lo planes
        const float* fa = reinterpret_cast<const float*>(sm + FA32) + r2 * 32 + c2 * 16;
        float f[16];
#pragma unroll
        for (int j = 0; j < 4; ++j) {
            float4 v = *reinterpret_cast<const float4*>(fa + j * 4);
            f[4 * j] = v.x; f[4 * j + 1] = v.y; f[4 * j + 2] = v.z; f[4 * j + 3] = v.w;
        }
        uint32_t* s = sm + buf * STG32;
        sts16(f, s, s + A_L32);
    };
    auto stsB = [&](int buf) {
        float f[16] = {stgB[0].x, stgB[0].y, stgB[0].z, stgB[0].w,
                       stgB[1].x, stgB[1].y, stgB[1].z, stgB[1].w,
                       stgB[2].x, stgB[2].y, stgB[2].z, stgB[2].w,
                       stgB[3].x, stgB[3].y, stgB[3].z, stgB[3].w};
        uint32_t* s = sm + buf * STG32;
        sts16(f, s + B_H32, s + B_L32);
    };

    auto compute_ks = [&](int buf, int ks) {
        const uint32_t base = sb + (uint32_t)buf * STG_BYTES;
        uint32_t bh[2][4], bl[2][4];
#pragma unroll
        for (int ntp = 0; ntp < 2; ++ntp) {
            uint32_t boff = (uint32_t)(((wn * 32 + ntp * 16 + bRow) * 40 + ks * 16 + bK8 * 8) * 2);
            LDSM4(bh[ntp], base + B_H32 * 4 + boff);
            LDSM4(bl[ntp], base + B_L32 * 4 + boff);
        }
#pragma unroll
        for (int mt = 0; mt < 4; ++mt) {
            uint32_t aoff = (uint32_t)(((wm * 64 + mt * 16 + aRow) * 40 + ks * 16 + aK8 * 8) * 2);
            uint32_t ah[4], al[4];
            LDSM4(ah, base + aoff);
            LDSM4(al, base + A_L32 * 4 + aoff);
#pragma unroll
            for (int ntp = 0; ntp < 2; ++ntp) {
                float* d0 = acc[mt][2 * ntp];
                float* d1 = acc[mt][2 * ntp + 1];
                mma16816(d0, ah, bh[ntp]);     mma16816(d1, ah, bh[ntp] + 2);
                mma16816(d0, ah, bl[ntp]);     mma16816(d1, ah, bl[ntp] + 2);
                mma16816(d0, al, bh[ntp]);     mma16816(d1, al, bh[ntp] + 2);
            }
        }
    };

    // prologue: stage 0 planes built; B(1) staged; A(1) streaming
    cpA(k_begin); CP_COMMIT();
    ldgB(k_begin);
    CP_WAIT0(); __syncthreads();
    convertA(0); stsB(0);
    if (S > 1) { cpA(k_begin + 32); CP_COMMIT(); ldgB(k_begin + 32); }
    __syncthreads();

    for (int s = 0; s < S; ++s) {
        const int cb = s & 1, nb = (s + 1) & 1;
        compute_ks(cb, 0);
        if (s + 1 < S) CP_WAIT0();
        __syncthreads();                              // cross-thread cp.async visibility (race fix)
        if (s + 1 < S) { convertA(nb); stsB(nb); }
        compute_ks(cb, 1);
        __syncthreads();
        if (s + 2 < S) { cpA(k_begin + (s + 2) * 32); CP_COMMIT(); ldgB(k_begin + (s + 2) * 32); }
    }

    // epilogue: fp32 partials
    const int g = lid >> 2, tig = lid & 3;
    float* Pbase = P + (size_t)(ksp * 128) * Ntot + ntile * 128;
#pragma unroll
    for (int mt = 0; mt < 4; ++mt) {
#pragma unroll
        for (int nt = 0; nt < 4; ++nt) {
            int row = wm * 64 + mt * 16 + g;
            int col = wn * 32 + nt * 8 + tig * 2;
            float* d0 = Pbase + (size_t)row * Ntot + col;
            float* d1 = Pbase + (size_t)(row + 8) * Ntot + col;
            *reinterpret_cast<float2*>(d0) = make_float2(acc[mt][nt][0], acc[mt][nt][1]);
            *reinterpret_cast<float2*>(d1) = make_float2(acc[mt][nt][2], acc[mt][nt][3]);
        }
    }
}

// ===================== RoI max pool — reciprocal-division emulation (LOAD-BEARING) =====================
// grid (128, 4): blockIdx.y selects a quarter of the 25088 outputs; bin math untouched.
__global__ void roipool_kernel(const float* __restrict__ x, const float* __restrict__ rois,
                               const int* __restrict__ ridx, float* __restrict__ pooled) {
    const int r = blockIdx.x;
    const float C7 = __uint_as_float(0x3E124925u);  // fl(1/7): matches XLA reciprocal-multiply
    __shared__ int hs[7], he[7], ws_[7], we_[7];
    if (threadIdx.x < 7) {
        const int p = threadIdx.x;
        float y1 = rintf(rois[r * 4 + 0] * 0.0625f);
        float x1 = rintf(rois[r * 4 + 1] * 0.0625f);
        float y2 = rintf(rois[r * 4 + 2] * 0.0625f);
        float x2 = rintf(rois[r * 4 + 3] * 0.0625f);
        float rh = fmaxf(y2 - y1 + 1.0f, 1.0f);
        float rw = fmaxf(x2 - x1 + 1.0f, 1.0f);
        float pf = (float)p;
        hs[p]  = (int)fminf(fmaxf(y1 + floorf((pf * rh) * C7), 0.0f), 37.0f);
        he[p]  = (int)fminf(fmaxf(y1 + ceilf(((pf + 1.0f) * rh) * C7), 0.0f), 37.0f);
        ws_[p] = (int)fminf(fmaxf(x1 + floorf((pf * rw) * C7), 0.0f), 37.0f);
        we_[p] = (int)fminf(fmaxf(x1 + ceilf(((pf + 1.0f) * rw) * C7), 0.0f), 37.0f);
    }
    __syncthreads();
    const float* xb = x + (size_t)ridx[r] * N_CH * (FH * FW);
    const float NEG = __int_as_float(0xff800000);
    const int qBeg = blockIdx.y * (N_CH * 49 / 4);
    const int qEnd = qBeg + (N_CH * 49 / 4);
    for (int q = qBeg + threadIdx.x; q < qEnd; q += blockDim.x) {
        const int c = q / 49;
        const int b = q - c * 49;
        const int ph = b / 7, pw = b - ph * 7;
        const float* xc = xb + c * (FH * FW);
        float mx = NEG;
        for (int h = hs[ph]; h < he[ph]; ++h) {
            const float* xr = xc + h * FW;
            for (int w = ws_[pw]; w < we_[pw]; ++w) mx = fmaxf(mx, xr[w]);
        }
        pooled[(size_t)r * K_FC6 + q] = (mx == NEG) ? 0.0f : mx;
    }
}

// ===================== reduce: sum split-K partials + bias + relu =====================
__global__ void reduce_kernel(const float* __restrict__ P, const float* __restrict__ bias,
                              float* __restrict__ out) {
    int idx = blockIdx.x * blockDim.x + threadIdx.x;
    if (idx >= 128 * NFC) return;
    int n = idx & (NFC - 1);
    float v = 0.0f;
#pragma unroll
    for (int s = 0; s < KSPLIT; ++s) v += P[(size_t)s * 128 * NFC + idx];
    out[idx] = fmaxf(v + bias[n], 0.0f);
}

// ===================== heads =====================
__global__ __launch_bounds__(256)
void heads_kernel(const float* __restrict__ fc7,
                  const float* __restrict__ Wsc, const float* __restrict__ bsc,
                  const float* __restrict__ Wloc, const float* __restrict__ bloc,
                  float* __restrict__ out) {
    int gw = (blockIdx.x * 256 + threadIdx.x) >> 5;
    int lane = threadIdx.x & 31;
    if (gw >= 128 * 105) return;
    int m = gw / 105, c = gw - m * 105;
    const float* wr = (c < 21) ? (Wsc + (size_t)c * NFC) : (Wloc + (size_t)(c - 21) * NFC);
    const float* arow = fc7 + (size_t)m * NFC;
    float s = 0.0f;
#pragma unroll 4
    for (int k = lane * 4; k < NFC; k += 128) {
        float4 a = *reinterpret_cast<const float4*>(arow + k);
        float4 w = *reinterpret_cast<const float4*>(wr + k);
        s += a.x * w.x + a.y * w.y + a.z * w.z + a.w * w.w;
    }
#pragma unroll
    for (int o = 16; o; o >>= 1) s += __shfl_down_sync(0xffffffffu, s, o);
    if (lane == 0) {
        if (c < 21) out[m * 21 + c] = s + bsc[c];
        else        out[128 * 21 + m * 84 + (c - 21)] = s + bloc[c - 21];
    }
}

// ===================== launch =====================
extern "C" void kernel_launch(void* const* d_in, const int* in_sizes, int n_in,
                              void* d_out, int out_size) {
    const float *x = nullptr, *rois = nullptr, *W1 = nullptr, *b1 = nullptr, *W2 = nullptr,
                *b2 = nullptr, *Wloc = nullptr, *bloc = nullptr, *Wsc = nullptr, *bsc = nullptr;
    const int* ridx = nullptr;
    for (int i = 0; i < n_in; ++i) {
        const int sz = in_sizes[i];
        const float* p = (const float*)d_in[i];
        switch (sz) {
            case 2 * N_CH * FH * FW: x = p; break;
            case N_ROIS * 4:         rois = p; break;
            case N_ROIS:             ridx = (const int*)d_in[i]; break;
            case NFC * K_FC6:        W1 = p; break;
            case NFC * NFC:          W2 = p; break;
            case 84 * NFC:           Wloc = p; break;
            case 21 * NFC:           Wsc = p; break;
            case 84:                 bloc = p; break;
            case 21:                 bsc = p; break;
            case NFC:                if (!b1) b1 = p; else b2 = p; break;
            default: break;
        }
    }
    float* out = (float*)d_out;

    float *pooled, *fc6, *fc7, *part;
    cudaGetSymbolAddress((void**)&pooled, g_pooled);
    cudaGetSymbolAddress((void**)&fc6, g_fc6);
    cudaGetSymbolAddress((void**)&fc7, g_fc7);
    cudaGetSymbolAddress((void**)&part, g_part);

    const int smem_gemm = 2 * 40960 + 16384;  // 98304 B -> 2 CTAs/SM
    cudaFuncSetAttribute((const void*)gemm_bf16x3,
                         cudaFuncAttributeMaxDynamicSharedMemorySize, smem_gemm);

    // 1. RoI max pool (channel-quartered grid)
    roipool_kernel<<<dim3(N_ROIS, 4), 256>>>(x, rois, ridx, pooled);
    // 2. fc6: 32 ntiles x 8 ksplit = 256 CTAs (2 CTAs/SM)
    gemm_bf16x3<<<32 * KSPLIT, 256, smem_gemm>>>(pooled, W1, part, K_FC6, K_FC6 / KSPLIT, NFC, 32);
    reduce_kernel<<<(128 * NFC + 255) / 256, 256>>>(part, b1, fc6);
    // 3. fc7
    gemm_bf16x3<<<32 * KSPLIT, 256, smem_gemm>>>(fc6, W2, part, NFC, NFC / KSPLIT, NFC, 32);
    reduce_kernel<<<(128 * NFC + 255) / 256, 256>>>(part, b2, fc7);
    // 4. heads
    heads_kernel<<<(128 * 105 * 32 + 255) / 256, 256>>>(fc7, Wsc, bsc, Wloc, bloc, out);
}